// round 6
// baseline (speedup 1.0000x reference)
#include <cuda_runtime.h>
#include <cuda_fp16.h>
#include <math.h>

#define HF 200
#define WF 200
#define CH 256
#define HO 7
#define WO 7
#define SUBS 2
#define HS (HO * SUBS)   // 14
#define WS (WO * SUBS)   // 14

#define ROW_BYTES (WF * CH * 2)   // 102400
#define COL_BYTES (CH * 2)        // 512

#define NPH 4                     // ph rows per block
#define NPOS (NPH * WO)           // 28 staged positions
#define SPITCH 264                // halves per position row (256 + 8 pad)

// Channels-last fp16 scratch copy: g_featTh[(y*WF + x)*CH + c]  (20.5 MB)
__device__ __align__(16) __half g_featTh[HF * WF * CH];

static __device__ __forceinline__ __half2 u2h2(unsigned u) {
    return *reinterpret_cast<__half2*>(&u);
}

// ---------------------------------------------------------------------------
// Kernel 1: transpose (C, H*W) f32 -> (H*W, C) fp16 (HBM-roofline bound)
// ---------------------------------------------------------------------------
__global__ void transpose_kernel(const float* __restrict__ in) {
    __shared__ float tile[32][33];
    const int p0 = blockIdx.x * 32;
    const int c0 = blockIdx.y * 32;
    const int tx = threadIdx.x;
    const int ty = threadIdx.y;

#pragma unroll
    for (int i = 0; i < 32; i += 8) {
        tile[ty + i][tx] = in[(size_t)(c0 + ty + i) * (HF * WF) + (p0 + tx)];
    }
    __syncthreads();

    const int tid = ty * 32 + tx;
#pragma unroll
    for (int it = 0; it < 2; it++) {
        const int idx = tid + it * 256;
        const int p_local = idx >> 4;
        const int k = idx & 15;
        __half2 h = __floats2half2_rn(tile[2 * k][p_local], tile[2 * k + 1][p_local]);
        *(__half2*)&g_featTh[(size_t)(p0 + p_local) * CH + c0 + 2 * k] = h;
    }
}

// ---------------------------------------------------------------------------
// Kernel 2: ROI align + 2x2 max subsample.
// Grid: (N, 2). Block: 224 threads, each owns (pw, c8) and loops over 4 ph
// rows (y=0: ph 0..3, y=1: ph 3..6; ph=3 duplicated bitwise-identically).
// x-geometry hoisted; 4 unrolled iterations give ptxas independent 16-load
// batches to pipeline across the L2 latency. Results staged in fp16 smem.
// ---------------------------------------------------------------------------
__global__ __launch_bounds__(224) void roialign_kernel(
    const float* __restrict__ rois,
    const float* __restrict__ img_size,
    float* __restrict__ out)
{
    const int n   = blockIdx.x;
    const int ph0 = blockIdx.y * 3;          // 0 or 3
    const int tid = threadIdx.x;

    __shared__ __align__(16) __half s_half[NPOS * SPITCH];  // 14.8 KB

    const float4 roi = ((const float4*)rois)[n];
    const float Hi = img_size[0];
    const float Wi = img_size[1];
    const float sy_scale = (HF - 1.0f) / (Hi - 1.0f);
    const float sx_scale = (WF - 1.0f) / (Wi - 1.0f);
    const float r0 = roi.x * sy_scale;
    const float r1 = roi.y * sx_scale;
    const float h_step = (roi.z * sy_scale - r0) / (float)HS;
    const float w_step = (roi.w * sx_scale - r1) / (float)WS;

    const int pw = tid >> 5;    // 0..6
    const int c8 = tid & 31;    // 0..31

    // --- loop-invariant x geometry ---
    const float xx0 = ((float)(2 * pw) + 0.5f) * w_step + r1;
    const float xx1 = xx0 + w_step;
    const int ix0 = __float2int_rd(xx0);
    const int ix1 = __float2int_rd(xx1);
    const __half2 fx0 = __float2half2_rn(xx0 - (float)ix0);
    const __half2 fx1 = __float2half2_rn(xx1 - (float)ix1);
    const unsigned cl0 = (unsigned)ix0 * COL_BYTES;
    const unsigned cl1 = (unsigned)ix1 * COL_BYTES;
    const unsigned cr0 = cl0 + COL_BYTES;
    const unsigned cr1 = cl1 + COL_BYTES;

    const char* fb = (const char*)g_featTh + c8 * 16;

#pragma unroll
    for (int k = 0; k < NPH; k++) {
        const int ph = ph0 + k;
        // direct (non-incremental) so both blocks produce bitwise-equal ph=3
        const float yy0 = ((float)(2 * ph) + 0.5f) * h_step + r0;
        const float yy1 = yy0 + h_step;
        const int iy0 = __float2int_rd(yy0);
        const int iy1 = __float2int_rd(yy1);
        const __half2 fy0 = __float2half2_rn(yy0 - (float)iy0);
        const __half2 fy1 = __float2half2_rn(yy1 - (float)iy1);

        const unsigned ru0 = (unsigned)iy0 * ROW_BYTES;
        const unsigned ru1 = (unsigned)iy1 * ROW_BYTES;
        const unsigned rd0 = ru0 + ROW_BYTES;
        const unsigned rd1 = ru1 + ROW_BYTES;

        uint4 v[16];
        v[ 0] = *(const uint4*)(fb + (ru0 + cl0));
        v[ 1] = *(const uint4*)(fb + (ru0 + cr0));
        v[ 2] = *(const uint4*)(fb + (rd0 + cl0));
        v[ 3] = *(const uint4*)(fb + (rd0 + cr0));
        v[ 4] = *(const uint4*)(fb + (ru0 + cl1));
        v[ 5] = *(const uint4*)(fb + (ru0 + cr1));
        v[ 6] = *(const uint4*)(fb + (rd0 + cl1));
        v[ 7] = *(const uint4*)(fb + (rd0 + cr1));
        v[ 8] = *(const uint4*)(fb + (ru1 + cl0));
        v[ 9] = *(const uint4*)(fb + (ru1 + cr0));
        v[10] = *(const uint4*)(fb + (rd1 + cl0));
        v[11] = *(const uint4*)(fb + (rd1 + cr0));
        v[12] = *(const uint4*)(fb + (ru1 + cl1));
        v[13] = *(const uint4*)(fb + (ru1 + cr1));
        v[14] = *(const uint4*)(fb + (rd1 + cl1));
        v[15] = *(const uint4*)(fb + (rd1 + cr1));

        __half2 best[4];
        const __half2 ninf = __float2half2_rn(-60000.0f);
#pragma unroll
        for (int j = 0; j < 4; j++) best[j] = ninf;

        const __half2 fxs[4] = {fx0, fx1, fx0, fx1};
        const __half2 fys[4] = {fy0, fy0, fy1, fy1};

#pragma unroll
        for (int s = 0; s < 4; s++) {
            const unsigned* pul = (const unsigned*)&v[s * 4 + 0];
            const unsigned* pur = (const unsigned*)&v[s * 4 + 1];
            const unsigned* pdl = (const unsigned*)&v[s * 4 + 2];
            const unsigned* pdr = (const unsigned*)&v[s * 4 + 3];
            const __half2 fx2 = fxs[s];
            const __half2 fy2 = fys[s];
#pragma unroll
            for (int j = 0; j < 4; j++) {
                const __half2 ul = u2h2(pul[j]);
                const __half2 ur = u2h2(pur[j]);
                const __half2 dl = u2h2(pdl[j]);
                const __half2 dr = u2h2(pdr[j]);
                const __half2 t = __hfma2(fx2, __hsub2(ur, ul), ul);
                const __half2 b = __hfma2(fx2, __hsub2(dr, dl), dl);
                const __half2 vv = __hfma2(fy2, __hsub2(b, t), t);
                best[j] = __hmax2(best[j], vv);
            }
        }

        // stage 8 halves (16B) at position (k*7 + pw), channels c8*8..+8
        *(uint4*)&s_half[(k * WO + pw) * SPITCH + c8 * 8] = *(const uint4*)best;
    }
    __syncthreads();

    // --- writeback: 28 pos x 256 ch; thread owns lpos = tid%28, c = c0+8k ---
    {
        const int lpos = tid % 28;      // 224 = 8*28: uniform
        const int c0   = tid / 28;      // 0..7
        const __half* sp = s_half + lpos * SPITCH;
        float* gp = out + (size_t)n * (CH * HO * WO) + ph0 * WO + lpos
                        + (size_t)c0 * (HO * WO);
#pragma unroll
        for (int k = 0; k < 32; k++) {
            *gp = __half2float(sp[c0 + 8 * k]);
            gp += 8 * (HO * WO);
        }
    }
}

extern "C" void kernel_launch(void* const* d_in, const int* in_sizes, int n_in,
                              void* d_out, int out_size) {
    const float* features = (const float*)d_in[0];  // (1, 256, 200, 200)
    const float* rois     = (const float*)d_in[1];  // (512, 4)
    const float* img_size = (const float*)d_in[2];  // (2,)
    float* out = (float*)d_out;                     // (512, 256, 7, 7)

    const int n_rois = in_sizes[1] / 4;

    dim3 tgrid(HF * WF / 32, CH / 32);
    dim3 tblock(32, 8);
    transpose_kernel<<<tgrid, tblock>>>(features);

    dim3 rgrid(n_rois, 2);
    roialign_kernel<<<rgrid, 224>>>(rois, img_size, out);
}